// round 7
// baseline (speedup 1.0000x reference)
#include <cuda_runtime.h>
#include <cuda_bf16.h>
#include <cstdint>

// Problem constants
#define BB 4
#define TT 4096
#define CC 1024
#define HH 16
#define DD 64
#define BT (BB*TT)          // 16384
#define KV_SPLIT 8

#define KEB 3072            // extended K in int8 bytes: [X1|X1|X2] x [W1|W2|W1]
#define NKIT (KEB/128)      // 24 k-chunks of 128 int8

// GEMM tiling (occ 2)
#define BM 128
#define BN 128
#define NSTAGE 3
#define STAGE_BYTES (2*16384)            // A 16KB + B 16KB
#define DYN_SMEM (NSTAGE*STAGE_BYTES)    // 96KB

// ---------------- scratch (device globals: allocation-free) ----------------
__device__ float g_Q[(size_t)BT*CC];
__device__ float g_K[(size_t)BT*CC];     // later reused as fp32 A buffer
__device__ float g_V[(size_t)BT*CC];
__device__ int8_t g_Xq[(size_t)BT*KEB];
__device__ int8_t g_Yq[(size_t)BT*KEB];
__device__ int8_t g_Aq[(size_t)BT*KEB];
__device__ int8_t g_Wqq[(size_t)CC*KEB];
__device__ int8_t g_Wkq[(size_t)CC*KEB];
__device__ int8_t g_Wvq[(size_t)CC*KEB];
__device__ int8_t g_Wpq[(size_t)CC*KEB];
__device__ unsigned g_amax[8];           // float bits, all values >= 0
__device__ float g_kvpart[(size_t)BB*HH*KV_SPLIT*DD*DD];
__device__ float g_kspart[(size_t)BB*HH*KV_SPLIT*DD];
__device__ float g_kv[(size_t)BB*HH*DD*DD];
__device__ float g_ksum[(size_t)BB*HH*DD];

// ---------------- helpers ----------------
__device__ __forceinline__ uint32_t smem_u32(const void* p) {
    uint32_t a;
    asm("{ .reg .u64 t; cvta.to.shared.u64 t, %1; cvt.u32.u64 %0, t; }"
        : "=r"(a) : "l"(p));
    return a;
}
__device__ __forceinline__ void cp16(uint32_t saddr, const void* gaddr) {
    asm volatile("cp.async.cg.shared.global [%0], [%1], 16;"
                 :: "r"(saddr), "l"(gaddr) : "memory");
}
__device__ __forceinline__ void cp_commit() {
    asm volatile("cp.async.commit_group;" ::: "memory");
}
__device__ __forceinline__ void cp_wait1() {
    asm volatile("cp.async.wait_group 1;" ::: "memory");
}
__device__ __forceinline__ void ldsm4(uint32_t* r, uint32_t addr) {
    asm volatile("ldmatrix.sync.aligned.m8n8.x4.shared.b16 {%0,%1,%2,%3}, [%4];"
                 : "=r"(r[0]), "=r"(r[1]), "=r"(r[2]), "=r"(r[3]) : "r"(addr));
}
__device__ __forceinline__ void mma16832(int* d, const uint32_t* a,
                                         const uint32_t* b) {
    asm volatile("mma.sync.aligned.m16n8k32.row.col.s32.s8.s8.s32 "
                 "{%0,%1,%2,%3}, {%4,%5,%6,%7}, {%8,%9}, {%0,%1,%2,%3};"
                 : "+r"(d[0]), "+r"(d[1]), "+r"(d[2]), "+r"(d[3])
                 : "r"(a[0]), "r"(a[1]), "r"(a[2]), "r"(a[3]),
                   "r"(b[0]), "r"(b[1]));
}

// ---------------- amax reset / reduce ----------------
__global__ void reset_amax_kernel()
{
    if (threadIdx.x < 8) g_amax[threadIdx.x] = 0u;
}

__global__ void amax_kernel(const float* __restrict__ src, int n, int slot)
{
    __shared__ float warpmax[8];
    float m = 0.f;
    int stride = gridDim.x * blockDim.x;
    for (int i = blockIdx.x * blockDim.x + threadIdx.x; i * 4 < n; i += stride) {
        float4 v = *(const float4*)(src + i * 4);
        m = fmaxf(m, fmaxf(fmaxf(fabsf(v.x), fabsf(v.y)),
                           fmaxf(fabsf(v.z), fabsf(v.w))));
    }
    #pragma unroll
    for (int o = 16; o; o >>= 1) m = fmaxf(m, __shfl_xor_sync(0xffffffffu, m, o));
    if ((threadIdx.x & 31) == 0) warpmax[threadIdx.x >> 5] = m;
    __syncthreads();
    if (threadIdx.x < 8) {
        m = warpmax[threadIdx.x];
        #pragma unroll
        for (int o = 4; o; o >>= 1) m = fmaxf(m, __shfl_xor_sync(0xffu, m, o));
        if (threadIdx.x == 0) atomicMax(&g_amax[slot], __float_as_uint(m));
    }
}

// ---------------- fp32 -> 2-word int8 quantization (extended layout) -------
// act   : segments [X1 | X1 | X2]
// weight: segments [W1 | W2 | W1]
__global__ void quant_kernel(const float* __restrict__ src,
                             int8_t* __restrict__ dst, int n, int slot,
                             int is_weight)
{
    int i = (blockIdx.x * blockDim.x + threadIdx.x) * 4;
    if (i >= n) return;
    float amax = __uint_as_float(g_amax[slot]);
    float s = amax * (1.f / 127.f);
    float inv = 127.f / amax;
    float4 v = *(const float4*)(src + i);
    int row = i >> 10, col = i & 1023;
    float f[4] = {v.x, v.y, v.z, v.w};
    char q1[4], q2[4];
    #pragma unroll
    for (int j = 0; j < 4; j++) {
        float x1 = rintf(f[j] * inv);
        float r = f[j] - x1 * s;
        float x2 = rintf(r * inv * 128.f);   // |x2| <= 64
        q1[j] = (char)(int)x1;
        q2[j] = (char)(int)x2;
    }
    char4 c1 = {q1[0], q1[1], q1[2], q1[3]};
    char4 c2 = {q2[0], q2[1], q2[2], q2[3]};
    size_t base = (size_t)row * KEB + col;
    *(char4*)(dst + base) = c1;
    if (is_weight) {
        *(char4*)(dst + base + 1024) = c2;
        *(char4*)(dst + base + 2048) = c1;
    } else {
        *(char4*)(dst + base + 1024) = c1;
        *(char4*)(dst + base + 2048) = c2;
    }
}

// ---------------- int8 mma GEMM: Out[M,1024] = dequant(Aq @ Wq^T) + bias ---
// Aq [M, 3072] int8 ([X1|X1|X2]), Wq [1024, 3072] int8 ([W1|W2|W1]).
// kt 0-7: X1*W1 (scale S); boundary: acc <<= 7; kt 8-23: cross terms (S/128).
// Warp tile 32x64: fused per-head softmax is warp-local.
__global__ __launch_bounds__(256, 2)
void gemm_tc(const int8_t* __restrict__ Aq,
             const int8_t* __restrict__ Wq,
             const float* __restrict__ bias,
             float* __restrict__ Out,
             int amax_a_slot, int amax_w_slot, int do_softmax)
{
    extern __shared__ char smraw[];
    const uint32_t smb = smem_u32(smraw);
    const int tid = threadIdx.x;
    const int wid = tid >> 5, lane = tid & 31;
    const int bm = blockIdx.y * BM, bn = blockIdx.x * BN;
    const int wm = (wid >> 1) * 32;       // warp m offset (0..96)
    const int wn = (wid & 1) * 64;        // warp n offset (0 / 64)

    const int lr = tid >> 3;              // 0..31
    const int lc = tid & 7;               // 16B chunk within 128B row
    const int8_t* Ag = Aq + (size_t)bm * KEB;
    const int8_t* Wg = Wq + (size_t)bn * KEB;

    int acc[2][8][4];
    #pragma unroll
    for (int i = 0; i < 2; i++)
        #pragma unroll
        for (int j = 0; j < 8; j++)
            #pragma unroll
            for (int e = 0; e < 4; e++) acc[i][j][e] = 0;

    auto issue_stage = [&](int kt, int st) {
        const uint32_t sa = smb + (uint32_t)st * STAGE_BYTES;
        const uint32_t sb = sa + 16384;
        const int kofs = kt * 128;
        #pragma unroll
        for (int i = 0; i < 4; i++) {
            int r = lr + i * 32;
            uint32_t so = (uint32_t)r * 128 + ((lc ^ (r & 7)) << 4);
            cp16(sa + so, Ag + (size_t)r * KEB + kofs + lc * 16);
            cp16(sb + so, Wg + (size_t)r * KEB + kofs + lc * 16);
        }
        cp_commit();
    };

    issue_stage(0, 0);
    issue_stage(1, 1);

    // per-lane ldmatrix row/col components (byte-identical to bf16 path)
    const int arow_l = (lane & 7) + ((lane >> 3) & 1) * 8;
    const int achk_l = lane >> 4;
    const int brow_l = (lane & 7) + (lane >> 4) * 8;
    const int bchk_l = (lane >> 3) & 1;

    for (int kt = 0; kt < NKIT; kt++) {
        cp_wait1();
        __syncthreads();
        if (kt + 2 < NKIT) issue_stage(kt + 2, (kt + 2) % NSTAGE);
        else cp_commit();

        const uint32_t sa = smb + (uint32_t)(kt % NSTAGE) * STAGE_BYTES;
        const uint32_t sb = sa + 16384;

        #pragma unroll
        for (int s = 0; s < 4; s++) {       // 4 x k32 per 128B stage row
            uint32_t a[2][4], bfr[8][2];
            #pragma unroll
            for (int mi = 0; mi < 2; mi++) {
                int r = wm + mi * 16 + arow_l;
                int c = s * 2 + achk_l;
                ldsm4(a[mi], sa + (uint32_t)r * 128 + ((c ^ (r & 7)) << 4));
            }
            #pragma unroll
            for (int j = 0; j < 4; j++) {
                uint32_t t[4];
                int r = wn + j * 16 + brow_l;
                int c = s * 2 + bchk_l;
                ldsm4(t, sb + (uint32_t)r * 128 + ((c ^ (r & 7)) << 4));
                bfr[j * 2 + 0][0] = t[0]; bfr[j * 2 + 0][1] = t[1];
                bfr[j * 2 + 1][0] = t[2]; bfr[j * 2 + 1][1] = t[3];
            }
            #pragma unroll
            for (int mi = 0; mi < 2; mi++)
                #pragma unroll
                for (int nj = 0; nj < 8; nj++)
                    mma16832(acc[mi][nj], a[mi], bfr[nj]);
        }

        if (kt == 7) {   // phase boundary: X1W1 done, promote to x128 domain
            #pragma unroll
            for (int mi = 0; mi < 2; mi++)
                #pragma unroll
                for (int nj = 0; nj < 8; nj++)
                    #pragma unroll
                    for (int e = 0; e < 4; e++) acc[mi][nj][e] <<= 7;
        }
        __syncthreads();
    }

    // epilogue: dequant + bias, optional per-head softmax
    float S = (__uint_as_float(g_amax[amax_a_slot]) * (1.f / 127.f)) *
              (__uint_as_float(g_amax[amax_w_slot]) * (1.f / 127.f)) *
              (1.f / 128.f);

    const int erow = lane >> 2, ecol = (lane & 3) * 2;
    float bcol[8][2];
    #pragma unroll
    for (int nj = 0; nj < 8; nj++) {
        int gn = bn + wn + nj * 8 + ecol;
        bcol[nj][0] = bias[gn];
        bcol[nj][1] = bias[gn + 1];
    }

    #pragma unroll
    for (int mi = 0; mi < 2; mi++) {
        #pragma unroll
        for (int half = 0; half < 2; half++) {
            float v[16];
            #pragma unroll
            for (int nj = 0; nj < 8; nj++) {
                v[nj * 2 + 0] = S * (float)acc[mi][nj][half * 2 + 0] + bcol[nj][0];
                v[nj * 2 + 1] = S * (float)acc[mi][nj][half * 2 + 1] + bcol[nj][1];
            }
            if (do_softmax) {
                float m = v[0];
                #pragma unroll
                for (int e = 1; e < 16; e++) m = fmaxf(m, v[e]);
                m = fmaxf(m, __shfl_xor_sync(0xffffffffu, m, 1));
                m = fmaxf(m, __shfl_xor_sync(0xffffffffu, m, 2));
                float s = 0.f;
                #pragma unroll
                for (int e = 0; e < 16; e++) { v[e] = __expf(v[e] - m); s += v[e]; }
                s += __shfl_xor_sync(0xffffffffu, s, 1);
                s += __shfl_xor_sync(0xffffffffu, s, 2);
                float inv = 1.0f / s;
                #pragma unroll
                for (int e = 0; e < 16; e++) v[e] *= inv;
            }
            int gm = bm + wm + mi * 16 + erow + half * 8;
            float* orow = Out + (size_t)gm * 1024 + bn + wn;
            #pragma unroll
            for (int nj = 0; nj < 8; nj++) {
                float2 o = { v[nj * 2], v[nj * 2 + 1] };
                *(float2*)(orow + nj * 8 + ecol) = o;
            }
        }
    }
}

// ---------------- kv = k^T v partials (and k column-sum partials) ----------
__global__ __launch_bounds__(256)
void kv_partial_kernel()
{
    const int bh = blockIdx.x;
    const int sp = blockIdx.y;
    const int b = bh >> 4, h = bh & 15;
    __shared__ float ks[64][68];
    __shared__ float vs[64][68];
    const int tid = threadIdx.x;
    const int txx = tid & 15, tyy = tid >> 4;
    const int t0 = sp * (TT / KV_SPLIT);

    float acc[4][4];
    #pragma unroll
    for (int i = 0; i < 4; i++)
        #pragma unroll
        for (int j = 0; j < 4; j++) acc[i][j] = 0.f;
    float kcol = 0.f;

    const float* kbase = g_K + (size_t)b * TT * CC + h * 64;
    const float* vbase = g_V + (size_t)b * TT * CC + h * 64;

    for (int tc = 0; tc < TT / KV_SPLIT; tc += 64) {
        #pragma unroll
        for (int i = 0; i < 4; i++) {
            int e = (tid + i * 256) * 4;
            int t = e >> 6, d = e & 63;
            size_t g = (size_t)(t0 + tc + t) * CC + d;
            *(float4*)&ks[t][d] = *(const float4*)(kbase + g);
            *(float4*)&vs[t][d] = *(const float4*)(vbase + g);
        }
        __syncthreads();

        if (tid < 64) {
            #pragma unroll 8
            for (int t = 0; t < 64; t++) kcol += ks[t][tid];
        }

        #pragma unroll 4
        for (int t = 0; t < 64; t++) {
            float a[4], bb[4];
            *(float4*)a  = *(const float4*)&ks[t][tyy * 4];
            *(float4*)bb = *(const float4*)&vs[t][txx * 4];
            #pragma unroll
            for (int i = 0; i < 4; i++)
                #pragma unroll
                for (int j = 0; j < 4; j++)
                    acc[i][j] += a[i] * bb[j];
        }
        __syncthreads();
    }

    float* outp = g_kvpart + (size_t)(bh * KV_SPLIT + sp) * (DD * DD);
    #pragma unroll
    for (int i = 0; i < 4; i++)
        *(float4*)(outp + (tyy * 4 + i) * 64 + txx * 4) = *(float4*)&acc[i][0];
    if (tid < 64)
        g_kspart[(size_t)(bh * KV_SPLIT + sp) * DD + tid] = kcol;
}

// ---------------- reduce partials ----------------
__global__ void kv_reduce_kernel()
{
    int idx = blockIdx.x * blockDim.x + threadIdx.x;
    if (idx < BB * HH * DD * DD) {
        int bh = idx / (DD * DD);
        int de = idx % (DD * DD);
        float s = 0.f;
        #pragma unroll
        for (int sp = 0; sp < KV_SPLIT; sp++)
            s += g_kvpart[(size_t)(bh * KV_SPLIT + sp) * (DD * DD) + de];
        g_kv[idx] = s;
    }
    if (idx < BB * HH * DD) {
        int bh = idx / DD, d = idx % DD;
        float s = 0.f;
        #pragma unroll
        for (int sp = 0; sp < KV_SPLIT; sp++)
            s += g_kspart[(size_t)(bh * KV_SPLIT + sp) * DD + d];
        g_ksum[idx] = s;
    }
}

// ---------------- combine: a = q + (q @ kv) * Dinv -> fp32 into g_K --------
__global__ __launch_bounds__(256)
void combine_kernel()
{
    const int bh = blockIdx.x;
    const int b = bh >> 4, h = bh & 15;
    const int tbase = blockIdx.y * 64;
    __shared__ float kvs[64][65];
    __shared__ float kss[64];
    const int tid = threadIdx.x;

    for (int i = tid; i < DD * DD; i += 256)
        kvs[i >> 6][i & 63] = g_kv[(size_t)bh * (DD * DD) + i];
    if (tid < 64) kss[tid] = g_ksum[(size_t)bh * DD + tid];
    __syncthreads();

    const int warp = tid >> 5, lane = tid & 31;
    for (int w = 0; w < 8; w++) {
        int t = tbase + warp * 8 + w;
        const float* qrow = g_Q + (size_t)(b * TT + t) * CC + h * 64;
        float q0 = qrow[lane], q1 = qrow[lane + 32];
        float dsum = q0 * kss[lane] + q1 * kss[lane + 32];
        #pragma unroll
        for (int o = 16; o; o >>= 1) dsum += __shfl_xor_sync(0xffffffffu, dsum, o);
        float dinv = 1.0f / dsum;
        float acc0 = 0.f, acc1 = 0.f;
        #pragma unroll
        for (int d = 0; d < 32; d++) {
            float qd = __shfl_sync(0xffffffffu, q0, d);
            acc0 += qd * kvs[d][lane];
            acc1 += qd * kvs[d][lane + 32];
        }
        #pragma unroll
        for (int d = 0; d < 32; d++) {
            float qd = __shfl_sync(0xffffffffu, q1, d);
            acc0 += qd * kvs[d + 32][lane];
            acc1 += qd * kvs[d + 32][lane + 32];
        }
        float* orow = g_K + (size_t)(b * TT + t) * CC + h * 64;  // K retired
        orow[lane]      = q0 + acc0 * dinv;
        orow[lane + 32] = q1 + acc1 * dinv;
    }
}

// ---------------- launcher ----------------
extern "C" void kernel_launch(void* const* d_in, const int* in_sizes, int n_in,
                              void* d_out, int out_size)
{
    const float* x  = (const float*)d_in[0];
    const float* y  = (const float*)d_in[1];
    const float* Wq = (const float*)d_in[2];
    const float* bq = (const float*)d_in[3];
    const float* Wk = (const float*)d_in[4];
    const float* bk = (const float*)d_in[5];
    const float* Wv = (const float*)d_in[6];
    const float* bv = (const float*)d_in[7];
    const float* Wp = (const float*)d_in[8];
    const float* bp = (const float*)d_in[9];
    float* out = (float*)d_out;

    float *pQ, *pK, *pV;
    int8_t *pXq, *pYq, *pAq, *pWqq, *pWkq, *pWvq, *pWpq;
    cudaGetSymbolAddress((void**)&pQ, g_Q);
    cudaGetSymbolAddress((void**)&pK, g_K);
    cudaGetSymbolAddress((void**)&pV, g_V);
    cudaGetSymbolAddress((void**)&pXq, g_Xq);
    cudaGetSymbolAddress((void**)&pYq, g_Yq);
    cudaGetSymbolAddress((void**)&pAq, g_Aq);
    cudaGetSymbolAddress((void**)&pWqq, g_Wqq);
    cudaGetSymbolAddress((void**)&pWkq, g_Wkq);
    cudaGetSymbolAddress((void**)&pWvq, g_Wvq);
    cudaGetSymbolAddress((void**)&pWpq, g_Wpq);

    cudaFuncSetAttribute(gemm_tc, cudaFuncAttributeMaxDynamicSharedMemorySize, DYN_SMEM);

    const int nX = BT * CC;     // 16.7M
    const int nW = CC * CC;     // 1.05M
    // amax slots: 0=x 1=y 2=Wq 3=Wk 4=Wv 5=Wp 6=A
    reset_amax_kernel<<<1, 32>>>();                     // launch 1
    amax_kernel<<<2048, 256>>>(x, nX, 0);               // 2
    amax_kernel<<<256, 256>>>(Wq, nW, 2);               // 3
    quant_kernel<<<nX / 4 / 256, 256>>>(x, pXq, nX, 0, 0);    // 4
    quant_kernel<<<nW / 4 / 256, 256>>>(Wq, pWqq, nW, 2, 1);  // 5

    dim3 gemmGrid(CC / BN, BT / BM);   // (8, 128)
    gemm_tc<<<gemmGrid, 256, DYN_SMEM>>>(pXq, pWqq, bq, pQ, 0, 2, 1);  // 6 (profiled)

    amax_kernel<<<2048, 256>>>(y, nX, 1);
    amax_kernel<<<256, 256>>>(Wk, nW, 3);
    amax_kernel<<<256, 256>>>(Wv, nW, 4);
    amax_kernel<<<256, 256>>>(Wp, nW, 5);
    quant_kernel<<<nX / 4 / 256, 256>>>(y, pYq, nX, 1, 0);
    quant_kernel<<<nW / 4 / 256, 256>>>(Wk, pWkq, nW, 3, 1);
    quant_kernel<<<nW / 4 / 256, 256>>>(Wv, pWvq, nW, 4, 1);
    quant_kernel<<<nW / 4 / 256, 256>>>(Wp, pWpq, nW, 5, 1);

    gemm_tc<<<gemmGrid, 256, DYN_SMEM>>>(pYq, pWkq, bk, pK, 1, 3, 1);
    gemm_tc<<<gemmGrid, 256, DYN_SMEM>>>(pYq, pWvq, bv, pV, 1, 4, 0);

    kv_partial_kernel<<<dim3(BB * HH, KV_SPLIT), 256>>>();
    kv_reduce_kernel<<<(BB * HH * DD * DD + 255) / 256, 256>>>();
    combine_kernel<<<dim3(BB * HH, TT / 64), 256>>>();  // writes fp32 A into g_K

    amax_kernel<<<2048, 256>>>(pK, nX, 6);
    quant_kernel<<<nX / 4 / 256, 256>>>(pK, pAq, nX, 6, 0);
    gemm_tc<<<gemmGrid, 256, DYN_SMEM>>>(pAq, pWpq, bp, out, 6, 5, 0);
}

// round 8
// speedup vs baseline: 2.5848x; 2.5848x over previous
#include <cuda_runtime.h>
#include <cuda_bf16.h>
#include <cstdint>

// Problem constants
#define BB 4
#define TT 4096
#define CC 1024
#define HH 16
#define DD 64
#define BT (BB*TT)          // 16384
#define KV_SPLIT 8

#define KE 3072             // extended K = 3*CC  ([hi|lo|hi] x [hi|hi|lo])
#define NKIT (KE/64)        // 48 k-chunks of 64

// GEMM tiling (occ 2)
#define BM 128
#define BN 128
#define NSTAGE 3
#define STAGE_BYTES (2*16384)            // A 16KB + B 16KB
#define DYN_SMEM (NSTAGE*STAGE_BYTES)    // 96KB

// ---------------- scratch (device globals: allocation-free) ----------------
__device__ float g_Q[(size_t)BT*CC];
__device__ float g_K[(size_t)BT*CC];
__device__ float g_V[(size_t)BT*CC];
__device__ __nv_bfloat16 g_Xext[(size_t)BT*KE];
__device__ __nv_bfloat16 g_Yext[(size_t)BT*KE];
__device__ __nv_bfloat16 g_Aext[(size_t)BT*KE];
__device__ __nv_bfloat16 g_Wqext[(size_t)CC*KE];
__device__ __nv_bfloat16 g_Wkext[(size_t)CC*KE];
__device__ __nv_bfloat16 g_Wvext[(size_t)CC*KE];
__device__ __nv_bfloat16 g_Wpext[(size_t)CC*KE];
__device__ float g_kvpart[(size_t)BB*HH*KV_SPLIT*DD*DD];
__device__ float g_kspart[(size_t)BB*HH*KV_SPLIT*DD];
__device__ float g_kv[(size_t)BB*HH*DD*DD];
__device__ float g_ksum[(size_t)BB*HH*DD];

// ---------------- helpers ----------------
__device__ __forceinline__ uint32_t smem_u32(const void* p) {
    uint32_t a;
    asm("{ .reg .u64 t; cvta.to.shared.u64 t, %1; cvt.u32.u64 %0, t; }"
        : "=r"(a) : "l"(p));
    return a;
}
__device__ __forceinline__ void cp16(uint32_t saddr, const void* gaddr) {
    asm volatile("cp.async.cg.shared.global [%0], [%1], 16;"
                 :: "r"(saddr), "l"(gaddr) : "memory");
}
__device__ __forceinline__ void cp_commit() {
    asm volatile("cp.async.commit_group;" ::: "memory");
}
__device__ __forceinline__ void cp_wait1() {
    asm volatile("cp.async.wait_group 1;" ::: "memory");
}
__device__ __forceinline__ void ldsm4(uint32_t* r, uint32_t addr) {
    asm volatile("ldmatrix.sync.aligned.m8n8.x4.shared.b16 {%0,%1,%2,%3}, [%4];"
                 : "=r"(r[0]), "=r"(r[1]), "=r"(r[2]), "=r"(r[3]) : "r"(addr));
}
__device__ __forceinline__ void mma16816(float* d, const uint32_t* a,
                                         const uint32_t* b) {
    asm volatile("mma.sync.aligned.m16n8k16.row.col.f32.bf16.bf16.f32 "
                 "{%0,%1,%2,%3}, {%4,%5,%6,%7}, {%8,%9}, {%0,%1,%2,%3};"
                 : "+f"(d[0]), "+f"(d[1]), "+f"(d[2]), "+f"(d[3])
                 : "r"(a[0]), "r"(a[1]), "r"(a[2]), "r"(a[3]),
                   "r"(b[0]), "r"(b[1]));
}

// ---------------- fp32 -> bf16 split into extended-K layout ----------------
// act   (is_weight=0): dst[r*3072 + c] = hi, +1024 = lo, +2048 = hi
// weight(is_weight=1): dst[r*3072 + c] = hi, +1024 = hi, +2048 = lo
__device__ __forceinline__ void split_body(const float* __restrict__ src,
                                           __nv_bfloat16* __restrict__ dst,
                                           int i, int is_weight)
{
    float4 v = *(const float4*)(src + i);
    int row = i >> 10, col = i & 1023;
    __nv_bfloat16 h[4], l[4];
    float f[4] = {v.x, v.y, v.z, v.w};
    #pragma unroll
    for (int j = 0; j < 4; j++) {
        h[j] = __float2bfloat16(f[j]);
        l[j] = __float2bfloat16(f[j] - __bfloat162float(h[j]));
    }
    ushort4 hv, lv;
    hv.x = __bfloat16_as_ushort(h[0]); hv.y = __bfloat16_as_ushort(h[1]);
    hv.z = __bfloat16_as_ushort(h[2]); hv.w = __bfloat16_as_ushort(h[3]);
    lv.x = __bfloat16_as_ushort(l[0]); lv.y = __bfloat16_as_ushort(l[1]);
    lv.z = __bfloat16_as_ushort(l[2]); lv.w = __bfloat16_as_ushort(l[3]);
    size_t base = (size_t)row * KE + col;
    *(ushort4*)(dst + base) = hv;
    if (is_weight) {
        *(ushort4*)(dst + base + 1024) = hv;
        *(ushort4*)(dst + base + 2048) = lv;
    } else {
        *(ushort4*)(dst + base + 1024) = lv;
        *(ushort4*)(dst + base + 2048) = hv;
    }
}

// z = 0..3: one weight each (n = CC*CC)
__global__ void split_weights_kernel(const float* __restrict__ w0,
                                     const float* __restrict__ w1,
                                     const float* __restrict__ w2,
                                     const float* __restrict__ w3)
{
    const float* src;
    __nv_bfloat16* dst;
    switch (blockIdx.z) {
        case 0:  src = w0; dst = g_Wqext; break;
        case 1:  src = w1; dst = g_Wkext; break;
        case 2:  src = w2; dst = g_Wvext; break;
        default: src = w3; dst = g_Wpext; break;
    }
    int i = (blockIdx.x * blockDim.x + threadIdx.x) * 4;
    if (i < CC * CC) split_body(src, dst, i, 1);
}

// z = 0: x -> Xext, z = 1: y -> Yext (n = BT*CC)
__global__ void split_acts_kernel(const float* __restrict__ x,
                                  const float* __restrict__ y)
{
    const float* src = blockIdx.z ? y : x;
    __nv_bfloat16* dst = blockIdx.z ? g_Yext : g_Xext;
    int i = (blockIdx.x * blockDim.x + threadIdx.x) * 4;
    if (i < BT * CC) split_body(src, dst, i, 0);
}

// ---------------- mma.sync GEMM: Out[M,1024] = Aext @ Wext^T + bias --------
// Batched over blockIdx.z (up to 3 independent GEMMs per launch).
// Warp tile 32x64: each warp owns one head's 64 cols -> warp-local softmax.
__global__ __launch_bounds__(256, 2)
void gemm_tc(const __nv_bfloat16* __restrict__ A0,
             const __nv_bfloat16* __restrict__ A1,
             const __nv_bfloat16* __restrict__ A2,
             const __nv_bfloat16* __restrict__ W0,
             const __nv_bfloat16* __restrict__ W1,
             const __nv_bfloat16* __restrict__ W2,
             const float* __restrict__ b0,
             const float* __restrict__ b1,
             const float* __restrict__ b2,
             float* __restrict__ O0,
             float* __restrict__ O1,
             float* __restrict__ O2,
             int softmax_mask)
{
    extern __shared__ char smraw[];
    const uint32_t smb = smem_u32(smraw);
    const int tid = threadIdx.x;
    const int wid = tid >> 5, lane = tid & 31;
    const int bm = blockIdx.y * BM, bn = blockIdx.x * BN;
    const int wm = (wid >> 1) * 32;       // warp m offset (0..96)
    const int wn = (wid & 1) * 64;        // warp n offset (0 / 64)

    const __nv_bfloat16* Aext;
    const __nv_bfloat16* Wext;
    const float* bias;
    float* Out;
    if (blockIdx.z == 0)      { Aext = A0; Wext = W0; bias = b0; Out = O0; }
    else if (blockIdx.z == 1) { Aext = A1; Wext = W1; bias = b1; Out = O1; }
    else                      { Aext = A2; Wext = W2; bias = b2; Out = O2; }
    const int do_softmax = (softmax_mask >> blockIdx.z) & 1;

    const int lr = tid >> 3;              // 0..31
    const int lc = tid & 7;               // 16B chunk within 128B row
    const __nv_bfloat16* Ag = Aext + (size_t)bm * KE;
    const __nv_bfloat16* Wg = Wext + (size_t)bn * KE;

    float acc[2][8][4];
    #pragma unroll
    for (int i = 0; i < 2; i++)
        #pragma unroll
        for (int j = 0; j < 8; j++)
            #pragma unroll
            for (int e = 0; e < 4; e++) acc[i][j][e] = 0.f;

    auto issue_stage = [&](int kt, int st) {
        const uint32_t sa = smb + (uint32_t)st * STAGE_BYTES;
        const uint32_t sb = sa + 16384;
        const int kofs = kt * 64;
        #pragma unroll
        for (int i = 0; i < 4; i++) {
            int r = lr + i * 32;
            uint32_t so = (uint32_t)r * 128 + ((lc ^ (r & 7)) << 4);
            cp16(sa + so, Ag + (size_t)r * KE + kofs + lc * 8);
            cp16(sb + so, Wg + (size_t)r * KE + kofs + lc * 8);
        }
        cp_commit();
    };

    issue_stage(0, 0);
    issue_stage(1, 1);

    // per-lane ldmatrix row/col components (validated in R3)
    const int arow_l = (lane & 7) + ((lane >> 3) & 1) * 8;
    const int achk_l = lane >> 4;
    const int brow_l = (lane & 7) + (lane >> 4) * 8;
    const int bchk_l = (lane >> 3) & 1;

    for (int kt = 0; kt < NKIT; kt++) {
        cp_wait1();
        __syncthreads();     // single barrier per iter: after this, all warps
                             // are in iter kt, so buffer (kt+2)%3 is free
        if (kt + 2 < NKIT) issue_stage(kt + 2, (kt + 2) % NSTAGE);
        else cp_commit();

        const uint32_t sa = smb + (uint32_t)(kt % NSTAGE) * STAGE_BYTES;
        const uint32_t sb = sa + 16384;

        #pragma unroll
        for (int s = 0; s < 4; s++) {
            uint32_t a[2][4], bfr[8][2];
            #pragma unroll
            for (int mi = 0; mi < 2; mi++) {
                int r = wm + mi * 16 + arow_l;
                int c = s * 2 + achk_l;
                ldsm4(a[mi], sa + (uint32_t)r * 128 + ((c ^ (r & 7)) << 4));
            }
            #pragma unroll
            for (int j = 0; j < 4; j++) {
                uint32_t t[4];
                int r = wn + j * 16 + brow_l;
                int c = s * 2 + bchk_l;
                ldsm4(t, sb + (uint32_t)r * 128 + ((c ^ (r & 7)) << 4));
                bfr[j * 2 + 0][0] = t[0]; bfr[j * 2 + 0][1] = t[1];
                bfr[j * 2 + 1][0] = t[2]; bfr[j * 2 + 1][1] = t[3];
            }
            #pragma unroll
            for (int mi = 0; mi < 2; mi++)
                #pragma unroll
                for (int nj = 0; nj < 8; nj++)
                    mma16816(acc[mi][nj], a[mi], bfr[nj]);
        }
    }

    // epilogue: +bias, optional per-head softmax (warp cols = one head)
    const int erow = lane >> 2, ecol = (lane & 3) * 2;
    float bcol[8][2];
    #pragma unroll
    for (int nj = 0; nj < 8; nj++) {
        int gn = bn + wn + nj * 8 + ecol;
        bcol[nj][0] = bias[gn];
        bcol[nj][1] = bias[gn + 1];
    }

    #pragma unroll
    for (int mi = 0; mi < 2; mi++) {
        #pragma unroll
        for (int half = 0; half < 2; half++) {      // rows erow / erow+8
            float v[16];
            #pragma unroll
            for (int nj = 0; nj < 8; nj++) {
                v[nj * 2 + 0] = acc[mi][nj][half * 2 + 0] + bcol[nj][0];
                v[nj * 2 + 1] = acc[mi][nj][half * 2 + 1] + bcol[nj][1];
            }
            if (do_softmax) {
                float m = v[0];
                #pragma unroll
                for (int e = 1; e < 16; e++) m = fmaxf(m, v[e]);
                m = fmaxf(m, __shfl_xor_sync(0xffffffffu, m, 1));
                m = fmaxf(m, __shfl_xor_sync(0xffffffffu, m, 2));
                float s = 0.f;
                #pragma unroll
                for (int e = 0; e < 16; e++) { v[e] = __expf(v[e] - m); s += v[e]; }
                s += __shfl_xor_sync(0xffffffffu, s, 1);
                s += __shfl_xor_sync(0xffffffffu, s, 2);
                float inv = 1.0f / s;
                #pragma unroll
                for (int e = 0; e < 16; e++) v[e] *= inv;
            }
            int gm = bm + wm + mi * 16 + erow + half * 8;
            float* orow = Out + (size_t)gm * 1024 + bn + wn;
            #pragma unroll
            for (int nj = 0; nj < 8; nj++) {
                float2 o = { v[nj * 2], v[nj * 2 + 1] };
                *(float2*)(orow + nj * 8 + ecol) = o;
            }
        }
    }
}

// ---------------- kv = k^T v partials (and k column-sum partials) ----------
__global__ __launch_bounds__(256)
void kv_partial_kernel()
{
    const int bh = blockIdx.x;
    const int sp = blockIdx.y;
    const int b = bh >> 4, h = bh & 15;
    __shared__ float ks[64][68];
    __shared__ float vs[64][68];
    const int tid = threadIdx.x;
    const int txx = tid & 15, tyy = tid >> 4;
    const int t0 = sp * (TT / KV_SPLIT);

    float acc[4][4];
    #pragma unroll
    for (int i = 0; i < 4; i++)
        #pragma unroll
        for (int j = 0; j < 4; j++) acc[i][j] = 0.f;
    float kcol = 0.f;

    const float* kbase = g_K + (size_t)b * TT * CC + h * 64;
    const float* vbase = g_V + (size_t)b * TT * CC + h * 64;

    for (int tc = 0; tc < TT / KV_SPLIT; tc += 64) {
        #pragma unroll
        for (int i = 0; i < 4; i++) {
            int e = (tid + i * 256) * 4;
            int t = e >> 6, d = e & 63;
            size_t g = (size_t)(t0 + tc + t) * CC + d;
            *(float4*)&ks[t][d] = *(const float4*)(kbase + g);
            *(float4*)&vs[t][d] = *(const float4*)(vbase + g);
        }
        __syncthreads();

        if (tid < 64) {
            #pragma unroll 8
            for (int t = 0; t < 64; t++) kcol += ks[t][tid];
        }

        #pragma unroll 4
        for (int t = 0; t < 64; t++) {
            float a[4], bb[4];
            *(float4*)a  = *(const float4*)&ks[t][tyy * 4];
            *(float4*)bb = *(const float4*)&vs[t][txx * 4];
            #pragma unroll
            for (int i = 0; i < 4; i++)
                #pragma unroll
                for (int j = 0; j < 4; j++)
                    acc[i][j] += a[i] * bb[j];
        }
        __syncthreads();
    }

    float* outp = g_kvpart + (size_t)(bh * KV_SPLIT + sp) * (DD * DD);
    #pragma unroll
    for (int i = 0; i < 4; i++)
        *(float4*)(outp + (tyy * 4 + i) * 64 + txx * 4) = *(float4*)&acc[i][0];
    if (tid < 64)
        g_kspart[(size_t)(bh * KV_SPLIT + sp) * DD + tid] = kcol;
}

// ---------------- reduce partials ----------------
__global__ void kv_reduce_kernel()
{
    int idx = blockIdx.x * blockDim.x + threadIdx.x;
    if (idx < BB * HH * DD * DD) {
        int bh = idx / (DD * DD);
        int de = idx % (DD * DD);
        float s = 0.f;
        #pragma unroll
        for (int sp = 0; sp < KV_SPLIT; sp++)
            s += g_kvpart[(size_t)(bh * KV_SPLIT + sp) * (DD * DD) + de];
        g_kv[idx] = s;
    }
    if (idx < BB * HH * DD) {
        int bh = idx / DD, d = idx % DD;
        float s = 0.f;
        #pragma unroll
        for (int sp = 0; sp < KV_SPLIT; sp++)
            s += g_kspart[(size_t)(bh * KV_SPLIT + sp) * DD + d];
        g_ksum[idx] = s;
    }
}

// ---------------- combine: a = q + (q @ kv) * Dinv -> ext bf16 layout ------
__global__ __launch_bounds__(256)
void combine_kernel()
{
    const int bh = blockIdx.x;
    const int b = bh >> 4, h = bh & 15;
    const int tbase = blockIdx.y * 64;
    __shared__ float kvs[64][65];
    __shared__ float kss[64];
    const int tid = threadIdx.x;

    for (int i = tid; i < DD * DD; i += 256)
        kvs[i >> 6][i & 63] = g_kv[(size_t)bh * (DD * DD) + i];
    if (tid < 64) kss[tid] = g_ksum[(size_t)bh * DD + tid];
    __syncthreads();

    const int warp = tid >> 5, lane = tid & 31;
    for (int w = 0; w < 8; w++) {
        int t = tbase + warp * 8 + w;
        const float* qrow = g_Q + (size_t)(b * TT + t) * CC + h * 64;
        float q0 = qrow[lane], q1 = qrow[lane + 32];
        float dsum = q0 * kss[lane] + q1 * kss[lane + 32];
        #pragma unroll
        for (int o = 16; o; o >>= 1) dsum += __shfl_xor_sync(0xffffffffu, dsum, o);
        float dinv = 1.0f / dsum;
        float acc0 = 0.f, acc1 = 0.f;
        #pragma unroll
        for (int d = 0; d < 32; d++) {
            float qd = __shfl_sync(0xffffffffu, q0, d);
            acc0 += qd * kvs[d][lane];
            acc1 += qd * kvs[d][lane + 32];
        }
        #pragma unroll
        for (int d = 0; d < 32; d++) {
            float qd = __shfl_sync(0xffffffffu, q1, d);
            acc0 += qd * kvs[d + 32][lane];
            acc1 += qd * kvs[d + 32][lane + 32];
        }
        float o0 = q0 + acc0 * dinv;
        float o1 = q1 + acc1 * dinv;
        __nv_bfloat16 h0 = __float2bfloat16(o0);
        __nv_bfloat16 h1 = __float2bfloat16(o1);
        __nv_bfloat16 l0 = __float2bfloat16(o0 - __bfloat162float(h0));
        __nv_bfloat16 l1 = __float2bfloat16(o1 - __bfloat162float(h1));
        size_t rb = (size_t)(b * TT + t) * KE + h * 64;
        g_Aext[rb + lane]             = h0;
        g_Aext[rb + lane + 32]        = h1;
        g_Aext[rb + 1024 + lane]      = l0;
        g_Aext[rb + 1024 + lane + 32] = l1;
        g_Aext[rb + 2048 + lane]      = h0;
        g_Aext[rb + 2048 + lane + 32] = h1;
    }
}

// ---------------- launcher ----------------
extern "C" void kernel_launch(void* const* d_in, const int* in_sizes, int n_in,
                              void* d_out, int out_size)
{
    const float* x  = (const float*)d_in[0];
    const float* y  = (const float*)d_in[1];
    const float* Wq = (const float*)d_in[2];
    const float* bq = (const float*)d_in[3];
    const float* Wk = (const float*)d_in[4];
    const float* bk = (const float*)d_in[5];
    const float* Wv = (const float*)d_in[6];
    const float* bv = (const float*)d_in[7];
    const float* Wp = (const float*)d_in[8];
    const float* bp = (const float*)d_in[9];
    float* out = (float*)d_out;

    float *pQ, *pK, *pV;
    __nv_bfloat16 *pX, *pY, *pA, *pWq, *pWk, *pWv, *pWp;
    cudaGetSymbolAddress((void**)&pQ, g_Q);
    cudaGetSymbolAddress((void**)&pK, g_K);
    cudaGetSymbolAddress((void**)&pV, g_V);
    cudaGetSymbolAddress((void**)&pX, g_Xext);
    cudaGetSymbolAddress((void**)&pY, g_Yext);
    cudaGetSymbolAddress((void**)&pA, g_Aext);
    cudaGetSymbolAddress((void**)&pWq, g_Wqext);
    cudaGetSymbolAddress((void**)&pWk, g_Wkext);
    cudaGetSymbolAddress((void**)&pWv, g_Wvext);
    cudaGetSymbolAddress((void**)&pWp, g_Wpext);

    cudaFuncSetAttribute(gemm_tc, cudaFuncAttributeMaxDynamicSharedMemorySize, DYN_SMEM);

    const int nX = BT * CC;     // 16.7M
    const int nW = CC * CC;     // 1.05M
    split_weights_kernel<<<dim3(nW / 4 / 256, 1, 4), 256>>>(Wq, Wk, Wv, Wp);
    split_acts_kernel<<<dim3(nX / 4 / 256, 1, 2), 256>>>(x, y);

    // Batched Q/K/V projection GEMMs (z = 0,1,2), softmax on z=0,1
    gemm_tc<<<dim3(CC / BN, BT / BM, 3), 256, DYN_SMEM>>>(
        pX, pY, pY,  pWq, pWk, pWv,  bq, bk, bv,  pQ, pK, pV,  0b011);

    kv_partial_kernel<<<dim3(BB * HH, KV_SPLIT), 256>>>();
    kv_reduce_kernel<<<(BB * HH * DD * DD + 255) / 256, 256>>>();
    combine_kernel<<<dim3(BB * HH, TT / 64), 256>>>();

    // Output projection (single GEMM in slot z=0)
    gemm_tc<<<dim3(CC / BN, BT / BM, 1), 256, DYN_SMEM>>>(
        pA, pA, pA,  pWp, pWp, pWp,  bp, bp, bp,  out, out, out,  0);
}